// round 10
// baseline (speedup 1.0000x reference)
#include <cuda_runtime.h>
#include <cstdint>

// Problem constants
#define Bn  4
#define Sn  2048
#define Dn  1024
#define Hn  16
#define DKn 64
#define Mn  (Bn * Sn)   // 8192

// Scratch (allocation-free: __device__ globals)
__device__ float g_Q[(size_t)Bn * Hn * Sn * DKn];     // [B,H,S,DK]
__device__ float g_K[(size_t)Bn * Hn * Sn * DKn];     // [B,H,S,DK]
__device__ float g_V[(size_t)Bn * Hn * Sn * DKn];     // [B,H,DK,S]  (transposed!)
__device__ float g_attn[(size_t)Bn * Sn * Dn];        // [B,S,D]

// ---------------------------------------------------------------------------
// Fast exp on the FMA pipe. Valid for x <= 0. Rel err ~1e-7.
// ---------------------------------------------------------------------------
__device__ __forceinline__ float fast_exp(float x) {
    float t = x * 1.44269504088896341f;
    t = fmaxf(t, -126.0f);
    float z = t + 12582912.0f;
    int   e = __float_as_int(z) - 0x4B400000;
    float fi = z - 12582912.0f;
    float f = t - fi;
    float p = 1.54035303933e-4f;
    p = fmaf(p, f, 1.33335581464e-3f);
    p = fmaf(p, f, 9.61812910763e-3f);
    p = fmaf(p, f, 5.55041086648e-2f);
    p = fmaf(p, f, 2.40226506959e-1f);
    p = fmaf(p, f, 6.93147180560e-1f);
    p = fmaf(p, f, 1.0f);
    return p * __int_as_float((e + 127) << 23);
}

// ---------------------------------------------------------------------------
// tf32 helpers
// ---------------------------------------------------------------------------
__device__ __forceinline__ uint32_t tf32_rna(float x) {
    uint32_t r;
    asm("cvt.rna.tf32.f32 %0, %1;" : "=r"(r) : "f"(x));
    return r;
}

__device__ __forceinline__ void mma_tf32_b(float* d, const uint32_t* a,
                                           uint32_t b0, uint32_t b1) {
    asm volatile(
        "mma.sync.aligned.m16n8k8.row.col.f32.tf32.tf32.f32 "
        "{%0,%1,%2,%3}, {%4,%5,%6,%7}, {%8,%9}, {%0,%1,%2,%3};\n"
        : "+f"(d[0]), "+f"(d[1]), "+f"(d[2]), "+f"(d[3])
        : "r"(a[0]), "r"(a[1]), "r"(a[2]), "r"(a[3]),
          "r"(b0), "r"(b1));
}

// ---------------------------------------------------------------------------
// GEMM: C[M,N] = A[M,K] @ W[N,K]^T + bias, single-pass tf32 mma m16n8k8.
// 128x128 block tile, BK=16, 256 threads, 8 warps as 2(M)x4(N) of 64x32.
// Double-buffered smem (2 stages), one barrier per k-step, LDG prefetch.
// Smem row stride 20: fragment LDS banks (4g+c+...)%32 conflict-free.
// MODE 1: write remapped: which 0->g_Q [B,H,S,DK], 1->g_K [B,H,S,DK],
//                         which 2->g_V TRANSPOSED [B,H,DK,S]
// MODE 0: A = g_attn, write plain [M,N] to outp (final projection)
// ---------------------------------------------------------------------------
#define SKW 20

template <int MODE>
__global__ __launch_bounds__(256) void gemm_k(const float* __restrict__ Ain,
                                              const float* __restrict__ W,
                                              const float* __restrict__ bias,
                                              float* __restrict__ outp,
                                              int which) {
    __shared__ __align__(16) uint32_t Ahs[2][128 * SKW];
    __shared__ __align__(16) uint32_t Whs[2][128 * SKW];

    const int tid  = threadIdx.x;
    const int lane = tid & 31;
    const int w    = tid >> 5;
    const int wm   = w >> 2;
    const int wn   = w & 3;
    const int g    = lane >> 2;
    const int c    = lane & 3;
    const int m0   = blockIdx.y << 7;
    const int n0   = blockIdx.x << 7;

    const float* A = (MODE == 0) ? g_attn : Ain;

    float acc[4][4][4];
#pragma unroll
    for (int mt = 0; mt < 4; mt++)
#pragma unroll
        for (int nt = 0; nt < 4; nt++)
#pragma unroll
            for (int r = 0; r < 4; r++) acc[mt][nt][r] = 0.f;

    const int lrow = tid >> 2;        // 0..63 (+64 on second)
    const int lq   = (tid & 3) << 2;  // 0,4,8,12

    const float* Aptr = A + (size_t)(m0 + lrow) * Dn + lq;
    const float* Wptr = W + (size_t)(n0 + lrow) * Dn + lq;

    // Prologue: load k=0 into stage 0
    {
        float4 a0 = *(const float4*)(Aptr);
        float4 a1 = *(const float4*)(Aptr + (size_t)64 * Dn);
        float4 w0 = *(const float4*)(Wptr);
        float4 w1 = *(const float4*)(Wptr + (size_t)64 * Dn);
        uint4 u;
        u.x = tf32_rna(a0.x); u.y = tf32_rna(a0.y);
        u.z = tf32_rna(a0.z); u.w = tf32_rna(a0.w);
        *(uint4*)&Ahs[0][lrow * SKW + lq] = u;
        u.x = tf32_rna(a1.x); u.y = tf32_rna(a1.y);
        u.z = tf32_rna(a1.z); u.w = tf32_rna(a1.w);
        *(uint4*)&Ahs[0][(lrow + 64) * SKW + lq] = u;
        u.x = tf32_rna(w0.x); u.y = tf32_rna(w0.y);
        u.z = tf32_rna(w0.z); u.w = tf32_rna(w0.w);
        *(uint4*)&Whs[0][lrow * SKW + lq] = u;
        u.x = tf32_rna(w1.x); u.y = tf32_rna(w1.y);
        u.z = tf32_rna(w1.z); u.w = tf32_rna(w1.w);
        *(uint4*)&Whs[0][(lrow + 64) * SKW + lq] = u;
    }
    __syncthreads();

    int s = 0;
    for (int k0 = 0; k0 < Dn; k0 += 16) {
        const bool has_next = (k0 + 16 < Dn);
        float4 na0, na1, nw0, nw1;
        if (has_next) {   // prefetch next panel into registers
            const float* ap = Aptr + k0 + 16;
            const float* wp = Wptr + k0 + 16;
            na0 = *(const float4*)(ap);
            na1 = *(const float4*)(ap + (size_t)64 * Dn);
            nw0 = *(const float4*)(wp);
            nw1 = *(const float4*)(wp + (size_t)64 * Dn);
        }

        // Compute from stage s
#pragma unroll
        for (int kk = 0; kk < 16; kk += 8) {
            uint32_t a_h[4][4], b_h[4][2];
#pragma unroll
            for (int mt = 0; mt < 4; mt++) {
                int base = ((wm << 6) + (mt << 4) + g) * SKW + kk + c;
                a_h[mt][0] = Ahs[s][base];
                a_h[mt][1] = Ahs[s][base + 8 * SKW];
                a_h[mt][2] = Ahs[s][base + 4];
                a_h[mt][3] = Ahs[s][base + 8 * SKW + 4];
            }
#pragma unroll
            for (int nt = 0; nt < 4; nt++) {
                int base = ((wn << 5) + (nt << 3) + g) * SKW + kk + c;
                b_h[nt][0] = Whs[s][base];
                b_h[nt][1] = Whs[s][base + 4];
            }
#pragma unroll
            for (int mt = 0; mt < 4; mt++)
#pragma unroll
                for (int nt = 0; nt < 4; nt++)
                    mma_tf32_b(acc[mt][nt], a_h[mt], b_h[nt][0], b_h[nt][1]);
        }

        if (has_next) {   // cvt + store prefetched panel into alternate stage
            int d = s ^ 1;
            uint4 u;
            u.x = tf32_rna(na0.x); u.y = tf32_rna(na0.y);
            u.z = tf32_rna(na0.z); u.w = tf32_rna(na0.w);
            *(uint4*)&Ahs[d][lrow * SKW + lq] = u;
            u.x = tf32_rna(na1.x); u.y = tf32_rna(na1.y);
            u.z = tf32_rna(na1.z); u.w = tf32_rna(na1.w);
            *(uint4*)&Ahs[d][(lrow + 64) * SKW + lq] = u;
            u.x = tf32_rna(nw0.x); u.y = tf32_rna(nw0.y);
            u.z = tf32_rna(nw0.z); u.w = tf32_rna(nw0.w);
            *(uint4*)&Whs[d][lrow * SKW + lq] = u;
            u.x = tf32_rna(nw1.x); u.y = tf32_rna(nw1.y);
            u.z = tf32_rna(nw1.z); u.w = tf32_rna(nw1.w);
            *(uint4*)&Whs[d][(lrow + 64) * SKW + lq] = u;
            __syncthreads();
        }
        s ^= 1;
    }

    // Epilogue
#pragma unroll
    for (int mt = 0; mt < 4; mt++) {
#pragma unroll
        for (int nt = 0; nt < 4; nt++) {
            int col = n0 + (wn << 5) + (nt << 3) + (c << 1);
            float b0 = bias[col], b1 = bias[col + 1];
#pragma unroll
            for (int half = 0; half < 2; half++) {
                int m = m0 + (wm << 6) + (mt << 4) + g + (half << 3);
                float vx = acc[mt][nt][half * 2 + 0] + b0;
                float vy = acc[mt][nt][half * 2 + 1] + b1;
                if (MODE == 1) {
                    int bb = m >> 11;
                    int ss = m & (Sn - 1);
                    int h  = col >> 6;
                    int d  = col & 63;
                    if (which == 2) {
                        // transposed: [B,H,DK,S]
                        float* outg = g_V;
                        outg[(((size_t)bb * Hn + h) * DKn + d) * Sn + ss] = vx;
                        outg[(((size_t)bb * Hn + h) * DKn + d + 1) * Sn + ss] = vy;
                    } else {
                        float* outg = (which == 0) ? g_Q : g_K;
                        float2 v = {vx, vy};
                        *(float2*)&outg[(((size_t)bb * Hn + h) * Sn + ss) * DKn + d] = v;
                    }
                } else {
                    float2 v = {vx, vy};
                    *(float2*)&outp[(size_t)m * Dn + col] = v;
                }
            }
        }
    }
}

// ---------------------------------------------------------------------------
// Flash attention on tensor cores (tf32 mma, single-pass). UNCHANGED.
// Block = 128 q rows of one (b,h); 8 warps, each owns 16 q rows (m16).
// ---------------------------------------------------------------------------
#define VSTR 68

__global__ __launch_bounds__(256, 2) void attn_kernel(const int* __restrict__ mask) {
    __shared__ __align__(16) uint32_t Ks[64 * VSTR];
    __shared__ __align__(16) uint32_t Vs[64 * VSTR];

    const int tid  = threadIdx.x;
    const int lane = tid & 31;
    const int w    = tid >> 5;
    const int g    = lane >> 2;
    const int c    = lane & 3;
    const int q0   = blockIdx.x << 7;
    const int h    = blockIdx.y;
    const int b    = blockIdx.z;

    const size_t head_off = ((size_t)b * Hn + h) * (size_t)Sn * DKn;
    const float* Qg = g_Q + head_off;
    const float* Kg = g_K + head_off;
    const float* Vg = g_V + head_off;              // [DK][S]
    const int rowA = q0 + w * 16 + g;
    const int rowB = rowA + 8;
    const int* mAp = mask + (size_t)b * Sn * Sn + (size_t)rowA * Sn;
    const int* mBp = mAp + 8 * Sn;

    uint32_t qf[8][4];
#pragma unroll
    for (int ks = 0; ks < 8; ks++) {
        qf[ks][0] = tf32_rna(Qg[(size_t)rowA * DKn + ks * 8 + c]);
        qf[ks][1] = tf32_rna(Qg[(size_t)rowB * DKn + ks * 8 + c]);
        qf[ks][2] = tf32_rna(Qg[(size_t)rowA * DKn + ks * 8 + c + 4]);
        qf[ks][3] = tf32_rna(Qg[(size_t)rowB * DKn + ks * 8 + c + 4]);
    }

    float O[8][4];
#pragma unroll
    for (int nb = 0; nb < 8; nb++)
#pragma unroll
        for (int r = 0; r < 4; r++) O[nb][r] = 0.f;
    float mxA = -1e30f, mxB = -1e30f, lA = 0.f, lB = 0.f;

    for (int kt = 0; kt < Sn / 64; kt++) {
        const int k0 = kt << 6;
        __syncthreads();

#pragma unroll
        for (int i = 0; i < 4; i++) {
            int idx = tid + (i << 8);
            int r  = idx >> 4;
            int f4 = (idx & 15) << 2;
            float4 k4 = *(const float4*)(Kg + (size_t)(k0 + r) * DKn + f4);
            uint4 uk;
            uk.x = tf32_rna(k4.x); uk.y = tf32_rna(k4.y);
            uk.z = tf32_rna(k4.z); uk.w = tf32_rna(k4.w);
            *(uint4*)&Ks[r * VSTR + f4] = uk;
            float4 v4 = *(const float4*)(Vg + (size_t)r * Sn + k0 + f4);
            uint4 uv;
            uv.x = tf32_rna(v4.x); uv.y = tf32_rna(v4.y);
            uv.z = tf32_rna(v4.z); uv.w = tf32_rna(v4.w);
            *(uint4*)&Vs[r * VSTR + f4] = uv;
        }
        __syncthreads();

        float sa[8][4];
#pragma unroll
        for (int nb = 0; nb < 8; nb++)
#pragma unroll
            for (int r = 0; r < 4; r++) sa[nb][r] = 0.f;

#pragma unroll
        for (int ks = 0; ks < 8; ks++) {
#pragma unroll
            for (int nb = 0; nb < 8; nb++) {
                uint32_t b0 = Ks[(nb * 8 + g) * VSTR + ks * 8 + c];
                uint32_t b1 = Ks[(nb * 8 + g) * VSTR + ks * 8 + c + 4];
                mma_tf32_b(sa[nb], qf[ks], b0, b1);
            }
        }

        float smA = -1e30f, smB = -1e30f;
#pragma unroll
        for (int nb = 0; nb < 8; nb++) {
            int2 m0 = *(const int2*)(mAp + k0 + nb * 8 + 2 * c);
            int2 m1 = *(const int2*)(mBp + k0 + nb * 8 + 2 * c);
            sa[nb][0] = m0.x ? sa[nb][0] * 0.125f : -1e9f;
            sa[nb][1] = m0.y ? sa[nb][1] * 0.125f : -1e9f;
            sa[nb][2] = m1.x ? sa[nb][2] * 0.125f : -1e9f;
            sa[nb][3] = m1.y ? sa[nb][3] * 0.125f : -1e9f;
            smA = fmaxf(smA, fmaxf(sa[nb][0], sa[nb][1]));
            smB = fmaxf(smB, fmaxf(sa[nb][2], sa[nb][3]));
        }
        smA = fmaxf(smA, __shfl_xor_sync(0xffffffffu, smA, 1));
        smA = fmaxf(smA, __shfl_xor_sync(0xffffffffu, smA, 2));
        smB = fmaxf(smB, __shfl_xor_sync(0xffffffffu, smB, 1));
        smB = fmaxf(smB, __shfl_xor_sync(0xffffffffu, smB, 2));

        float mnA = fmaxf(mxA, smA), mnB = fmaxf(mxB, smB);
        float aA = fast_exp(mxA - mnA), aB = fast_exp(mxB - mnB);
        mxA = mnA; mxB = mnB;

        float rsA = 0.f, rsB = 0.f;
#pragma unroll
        for (int nb = 0; nb < 8; nb++) {
            sa[nb][0] = fast_exp(sa[nb][0] - mnA);
            sa[nb][1] = fast_exp(sa[nb][1] - mnA);
            sa[nb][2] = fast_exp(sa[nb][2] - mnB);
            sa[nb][3] = fast_exp(sa[nb][3] - mnB);
            rsA += sa[nb][0] + sa[nb][1];
            rsB += sa[nb][2] + sa[nb][3];
        }
        rsA += __shfl_xor_sync(0xffffffffu, rsA, 1);
        rsA += __shfl_xor_sync(0xffffffffu, rsA, 2);
        rsB += __shfl_xor_sync(0xffffffffu, rsB, 1);
        rsB += __shfl_xor_sync(0xffffffffu, rsB, 2);
        lA = lA * aA + rsA;
        lB = lB * aB + rsB;

#pragma unroll
        for (int nb = 0; nb < 8; nb++) {
            O[nb][0] *= aA; O[nb][1] *= aA;
            O[nb][2] *= aB; O[nb][3] *= aB;
        }

        const int srcLo = (lane & 28) | (c >> 1);
        const int srcHi = srcLo + 2;
        const bool odd = (c & 1);
#pragma unroll
        for (int ks = 0; ks < 8; ks++) {
            float v0 = __shfl_sync(0xffffffffu, sa[ks][0], srcLo);
            float v1 = __shfl_sync(0xffffffffu, sa[ks][1], srcLo);
            float v2 = __shfl_sync(0xffffffffu, sa[ks][2], srcLo);
            float v3 = __shfl_sync(0xffffffffu, sa[ks][3], srcLo);
            float w0 = __shfl_sync(0xffffffffu, sa[ks][0], srcHi);
            float w1 = __shfl_sync(0xffffffffu, sa[ks][1], srcHi);
            float w2 = __shfl_sync(0xffffffffu, sa[ks][2], srcHi);
            float w3 = __shfl_sync(0xffffffffu, sa[ks][3], srcHi);
            uint32_t af[4];
            af[0] = tf32_rna(odd ? v1 : v0);
            af[1] = tf32_rna(odd ? v3 : v2);
            af[2] = tf32_rna(odd ? w1 : w0);
            af[3] = tf32_rna(odd ? w3 : w2);
#pragma unroll
            for (int nb = 0; nb < 8; nb++) {
                uint32_t b0 = Vs[(nb * 8 + g) * VSTR + ks * 8 + c];
                uint32_t b1 = Vs[(nb * 8 + g) * VSTR + ks * 8 + c + 4];
                mma_tf32_b(O[nb], af, b0, b1);
            }
        }
    }

    const float invA = 1.0f / lA, invB = 1.0f / lB;
    float* ogA = g_attn + ((size_t)b * Sn + rowA) * Dn + h * DKn;
    float* ogB = ogA + 8 * Dn;
#pragma unroll
    for (int nb = 0; nb < 8; nb++) {
        int col = nb * 8 + 2 * c;
        float2 va = {O[nb][0] * invA, O[nb][1] * invA};
        float2 vb = {O[nb][2] * invB, O[nb][3] * invB};
        *(float2*)&ogA[col] = va;
        *(float2*)&ogB[col] = vb;
    }
}

// ---------------------------------------------------------------------------
// kernel_launch: 5 kernel launches on the default stream (graph-capturable)
// ---------------------------------------------------------------------------
extern "C" void kernel_launch(void* const* d_in, const int* in_sizes, int n_in,
                              void* d_out, int out_size) {
    (void)in_sizes; (void)n_in; (void)out_size;
    const float* query = (const float*)d_in[0];
    const float* key   = (const float*)d_in[1];
    const float* value = (const float*)d_in[2];
    const int*   mask  = (const int*)d_in[3];
    const float* Wq = (const float*)d_in[4];
    const float* bq = (const float*)d_in[5];
    const float* Wk = (const float*)d_in[6];
    const float* bk = (const float*)d_in[7];
    const float* Wv = (const float*)d_in[8];
    const float* bv = (const float*)d_in[9];
    const float* Wo = (const float*)d_in[10];
    const float* bo = (const float*)d_in[11];

    dim3 gg(Dn / 128, Mn / 128);   // (8, 64)
    gemm_k<1><<<gg, 256>>>(query, Wq, bq, nullptr, 0);
    gemm_k<1><<<gg, 256>>>(key,   Wk, bk, nullptr, 1);
    gemm_k<1><<<gg, 256>>>(value, Wv, bv, nullptr, 2);

    attn_kernel<<<dim3(Sn / 128, Hn, Bn), 256>>>(mask);

    gemm_k<0><<<gg, 256>>>(nullptr, Wo, bo, (float*)d_out, 0);
}

// round 11
// speedup vs baseline: 1.4036x; 1.4036x over previous
#include <cuda_runtime.h>
#include <cuda_fp16.h>
#include <cstdint>

// Problem constants
#define Bn  4
#define Sn  2048
#define Dn  1024
#define Hn  16
#define DKn 64
#define Mn  (Bn * Sn)   // 8192

// Scratch (allocation-free: __device__ globals)
__device__ float g_Q[(size_t)Bn * Hn * Sn * DKn];     // [B,H,S,DK]
__device__ float g_K[(size_t)Bn * Hn * Sn * DKn];     // [B,H,S,DK]
__device__ float g_V[(size_t)Bn * Hn * Sn * DKn];     // [B,H,DK,S]  (transposed!)
__device__ float g_attn[(size_t)Bn * Sn * Dn];        // [B,S,D]

// ---------------------------------------------------------------------------
// Fast exp on the FMA pipe. Valid for x <= 0. Rel err ~1e-7.
// ---------------------------------------------------------------------------
__device__ __forceinline__ float fast_exp(float x) {
    float t = x * 1.44269504088896341f;
    t = fmaxf(t, -126.0f);
    float z = t + 12582912.0f;
    int   e = __float_as_int(z) - 0x4B400000;
    float fi = z - 12582912.0f;
    float f = t - fi;
    float p = 1.54035303933e-4f;
    p = fmaf(p, f, 1.33335581464e-3f);
    p = fmaf(p, f, 9.61812910763e-3f);
    p = fmaf(p, f, 5.55041086648e-2f);
    p = fmaf(p, f, 2.40226506959e-1f);
    p = fmaf(p, f, 6.93147180560e-1f);
    p = fmaf(p, f, 1.0f);
    return p * __int_as_float((e + 127) << 23);
}

// ---------------------------------------------------------------------------
// fp16 helpers (fp16 has the same 11-bit mantissa as tf32: precision-neutral
// swap, but 2x MACs/instr and 2 values per 32-bit register)
// ---------------------------------------------------------------------------
__device__ __forceinline__ uint32_t pack_h2(float lo, float hi) {
    __half2 h = __floats2half2_rn(lo, hi);
    return *(uint32_t*)&h;
}

// mma.m16n8k16 row.col f32.f16.f16.f32
__device__ __forceinline__ void mma_f16(float* d, const uint32_t* a,
                                        uint32_t b0, uint32_t b1) {
    asm volatile(
        "mma.sync.aligned.m16n8k16.row.col.f32.f16.f16.f32 "
        "{%0,%1,%2,%3}, {%4,%5,%6,%7}, {%8,%9}, {%0,%1,%2,%3};\n"
        : "+f"(d[0]), "+f"(d[1]), "+f"(d[2]), "+f"(d[3])
        : "r"(a[0]), "r"(a[1]), "r"(a[2]), "r"(a[3]),
          "r"(b0), "r"(b1));
}

// ---------------------------------------------------------------------------
// GEMM: C[M,N] = A[M,K] @ W[N,K]^T + bias, fp16 mma m16n8k16, fp32 accum.
// 128x128 block tile, BK=16, 256 threads, 8 warps as 2(M)x4(N) of 64x32.
// Double-buffered smem (2 stages), one barrier per k-step, LDG prefetch.
// Panels stored as fp16x2 words, row stride 12 words (8 data + 4 pad):
// fragment LDS banks = 12g + c (+0/+4) mod 32 -> conflict-free.
// MODE 1: write remapped: which 0->g_Q [B,H,S,DK], 1->g_K [B,H,S,DK],
//                         which 2->g_V TRANSPOSED [B,H,DK,S]
// MODE 0: A = g_attn, write plain [M,N] to outp (final projection)
// ---------------------------------------------------------------------------
#define GRS 12   // words per 16-k row (8 fp16x2 data + 4 pad)

template <int MODE>
__global__ __launch_bounds__(256) void gemm_k(const float* __restrict__ Ain,
                                              const float* __restrict__ W,
                                              const float* __restrict__ bias,
                                              float* __restrict__ outp,
                                              int which) {
    __shared__ __align__(16) uint32_t Ahs[2][128 * GRS];
    __shared__ __align__(16) uint32_t Whs[2][128 * GRS];

    const int tid  = threadIdx.x;
    const int lane = tid & 31;
    const int w    = tid >> 5;
    const int wm   = w >> 2;
    const int wn   = w & 3;
    const int g    = lane >> 2;
    const int c    = lane & 3;
    const int m0   = blockIdx.y << 7;
    const int n0   = blockIdx.x << 7;

    const float* A = (MODE == 0) ? g_attn : Ain;

    float acc[4][4][4];
#pragma unroll
    for (int mt = 0; mt < 4; mt++)
#pragma unroll
        for (int nt = 0; nt < 4; nt++)
#pragma unroll
            for (int r = 0; r < 4; r++) acc[mt][nt][r] = 0.f;

    const int lrow = tid >> 2;        // 0..63 (+64 on second)
    const int lq   = (tid & 3) << 2;  // 0,4,8,12
    const int lw   = lq >> 1;         // word offset 0,2,4,6

    const float* Aptr = A + (size_t)(m0 + lrow) * Dn + lq;
    const float* Wptr = W + (size_t)(n0 + lrow) * Dn + lq;

    // Prologue: load k=0 into stage 0
    {
        float4 a0 = *(const float4*)(Aptr);
        float4 a1 = *(const float4*)(Aptr + (size_t)64 * Dn);
        float4 w0 = *(const float4*)(Wptr);
        float4 w1 = *(const float4*)(Wptr + (size_t)64 * Dn);
        uint2 u;
        u.x = pack_h2(a0.x, a0.y); u.y = pack_h2(a0.z, a0.w);
        *(uint2*)&Ahs[0][lrow * GRS + lw] = u;
        u.x = pack_h2(a1.x, a1.y); u.y = pack_h2(a1.z, a1.w);
        *(uint2*)&Ahs[0][(lrow + 64) * GRS + lw] = u;
        u.x = pack_h2(w0.x, w0.y); u.y = pack_h2(w0.z, w0.w);
        *(uint2*)&Whs[0][lrow * GRS + lw] = u;
        u.x = pack_h2(w1.x, w1.y); u.y = pack_h2(w1.z, w1.w);
        *(uint2*)&Whs[0][(lrow + 64) * GRS + lw] = u;
    }
    __syncthreads();

    int s = 0;
    for (int k0 = 0; k0 < Dn; k0 += 16) {
        const bool has_next = (k0 + 16 < Dn);
        float4 na0, na1, nw0, nw1;
        if (has_next) {
            const float* ap = Aptr + k0 + 16;
            const float* wp = Wptr + k0 + 16;
            na0 = *(const float4*)(ap);
            na1 = *(const float4*)(ap + (size_t)64 * Dn);
            nw0 = *(const float4*)(wp);
            nw1 = *(const float4*)(wp + (size_t)64 * Dn);
        }

        // Compute one k16 panel: 16 mma m16n8k16
        {
            uint32_t af[4][4], bf[4][2];
#pragma unroll
            for (int mt = 0; mt < 4; mt++) {
                int base = ((wm << 6) + (mt << 4) + g) * GRS + c;
                af[mt][0] = Ahs[s][base];
                af[mt][1] = Ahs[s][base + 8 * GRS];
                af[mt][2] = Ahs[s][base + 4];
                af[mt][3] = Ahs[s][base + 8 * GRS + 4];
            }
#pragma unroll
            for (int nt = 0; nt < 4; nt++) {
                int base = ((wn << 5) + (nt << 3) + g) * GRS + c;
                bf[nt][0] = Whs[s][base];
                bf[nt][1] = Whs[s][base + 4];
            }
#pragma unroll
            for (int mt = 0; mt < 4; mt++)
#pragma unroll
                for (int nt = 0; nt < 4; nt++)
                    mma_f16(acc[mt][nt], af[mt], bf[nt][0], bf[nt][1]);
        }

        if (has_next) {
            int d = s ^ 1;
            uint2 u;
            u.x = pack_h2(na0.x, na0.y); u.y = pack_h2(na0.z, na0.w);
            *(uint2*)&Ahs[d][lrow * GRS + lw] = u;
            u.x = pack_h2(na1.x, na1.y); u.y = pack_h2(na1.z, na1.w);
            *(uint2*)&Ahs[d][(lrow + 64) * GRS + lw] = u;
            u.x = pack_h2(nw0.x, nw0.y); u.y = pack_h2(nw0.z, nw0.w);
            *(uint2*)&Whs[d][lrow * GRS + lw] = u;
            u.x = pack_h2(nw1.x, nw1.y); u.y = pack_h2(nw1.z, nw1.w);
            *(uint2*)&Whs[d][(lrow + 64) * GRS + lw] = u;
            __syncthreads();
        }
        s ^= 1;
    }

    // Epilogue (fp32 accum): C-frag rows g/g+8, cols 2c/2c+1
#pragma unroll
    for (int mt = 0; mt < 4; mt++) {
#pragma unroll
        for (int nt = 0; nt < 4; nt++) {
            int col = n0 + (wn << 5) + (nt << 3) + (c << 1);
            float b0 = bias[col], b1 = bias[col + 1];
#pragma unroll
            for (int half = 0; half < 2; half++) {
                int m = m0 + (wm << 6) + (mt << 4) + g + (half << 3);
                float vx = acc[mt][nt][half * 2 + 0] + b0;
                float vy = acc[mt][nt][half * 2 + 1] + b1;
                if (MODE == 1) {
                    int bb = m >> 11;
                    int ss = m & (Sn - 1);
                    int h  = col >> 6;
                    int d  = col & 63;
                    if (which == 2) {
                        float* outg = g_V;   // [B,H,DK,S]
                        outg[(((size_t)bb * Hn + h) * DKn + d) * Sn + ss] = vx;
                        outg[(((size_t)bb * Hn + h) * DKn + d + 1) * Sn + ss] = vy;
                    } else {
                        float* outg = (which == 0) ? g_Q : g_K;
                        float2 v = {vx, vy};
                        *(float2*)&outg[(((size_t)bb * Hn + h) * Sn + ss) * DKn + d] = v;
                    }
                } else {
                    float2 v = {vx, vy};
                    *(float2*)&outp[(size_t)m * Dn + col] = v;
                }
            }
        }
    }
}

// ---------------------------------------------------------------------------
// Flash attention, fp16 mma m16n8k16 (fp32 accumulate).
// Block = 128 q rows of one (b,h); 8 warps, each owns 16 q rows.
// 32 KV-tiles of 64. Ks[kv][dk] and Vs[dk][kv] as fp16x2, row stride 36 words
// (frag banks 4g+8kk+c : conflict-free). Q frags register-resident, scale
// 1/8 folded into Q. PV A-frags come straight from S C-frags (fp16 k-pairs
// {2c,2c+1} == C-frag col pairs) — zero shuffles.
// ---------------------------------------------------------------------------
#define KRS 36   // words per tile row (32 fp16x2 data + 4 pad)

__global__ __launch_bounds__(256, 2) void attn_kernel(const int* __restrict__ mask) {
    __shared__ __align__(16) uint32_t Ks[64 * KRS];
    __shared__ __align__(16) uint32_t Vs[64 * KRS];

    const int tid  = threadIdx.x;
    const int lane = tid & 31;
    const int w    = tid >> 5;
    const int g    = lane >> 2;
    const int c    = lane & 3;
    const int q0   = blockIdx.x << 7;
    const int h    = blockIdx.y;
    const int b    = blockIdx.z;

    const size_t head_off = ((size_t)b * Hn + h) * (size_t)Sn * DKn;
    const float* Qg = g_Q + head_off;
    const float* Kg = g_K + head_off;
    const float* Vg = g_V + head_off;              // [DK][S]
    const int rowA = q0 + w * 16 + g;
    const int rowB = rowA + 8;
    const int* mAp = mask + (size_t)b * Sn * Sn + (size_t)rowA * Sn;
    const int* mBp = mAp + 8 * Sn;

    // Q fragments (fp16x2, 1/8 scale folded in), loaded once
    uint32_t qf[4][4];
#pragma unroll
    for (int kk = 0; kk < 4; kk++) {
        const float* qa = Qg + (size_t)rowA * DKn + kk * 16;
        const float* qb = Qg + (size_t)rowB * DKn + kk * 16;
        qf[kk][0] = pack_h2(qa[2 * c] * 0.125f,     qa[2 * c + 1] * 0.125f);
        qf[kk][1] = pack_h2(qb[2 * c] * 0.125f,     qb[2 * c + 1] * 0.125f);
        qf[kk][2] = pack_h2(qa[2 * c + 8] * 0.125f, qa[2 * c + 9] * 0.125f);
        qf[kk][3] = pack_h2(qb[2 * c + 8] * 0.125f, qb[2 * c + 9] * 0.125f);
    }

    float O[8][4];
#pragma unroll
    for (int nb = 0; nb < 8; nb++)
#pragma unroll
        for (int r = 0; r < 4; r++) O[nb][r] = 0.f;
    float mxA = -1e30f, mxB = -1e30f, lA = 0.f, lB = 0.f;

    for (int kt = 0; kt < Sn / 64; kt++) {
        const int k0 = kt << 6;
        __syncthreads();

        // Load K tile [kv][dk] and V tile [dk][kv], cvt to fp16x2
#pragma unroll
        for (int i = 0; i < 4; i++) {
            int idx = tid + (i << 8);
            int r  = idx >> 4;
            int f4 = (idx & 15) << 2;
            float4 k4 = *(const float4*)(Kg + (size_t)(k0 + r) * DKn + f4);
            uint2 pk;
            pk.x = pack_h2(k4.x, k4.y); pk.y = pack_h2(k4.z, k4.w);
            *(uint2*)&Ks[r * KRS + (f4 >> 1)] = pk;
            float4 v4 = *(const float4*)(Vg + (size_t)r * Sn + k0 + f4);
            uint2 pv;
            pv.x = pack_h2(v4.x, v4.y); pv.y = pack_h2(v4.z, v4.w);
            *(uint2*)&Vs[r * KRS + (f4 >> 1)] = pv;
        }
        __syncthreads();

        // S = (Q/8) @ K^T : 4 k16 steps x 8 n-blocks
        float sa[8][4];
#pragma unroll
        for (int nb = 0; nb < 8; nb++)
#pragma unroll
            for (int r = 0; r < 4; r++) sa[nb][r] = 0.f;

#pragma unroll
        for (int kk = 0; kk < 4; kk++) {
#pragma unroll
            for (int nb = 0; nb < 8; nb++) {
                int base = (nb * 8 + g) * KRS + 8 * kk + c;
                mma_f16(sa[nb], qf[kk], Ks[base], Ks[base + 4]);
            }
        }

        // Mask (scale already folded) + row max
        float smA = -1e30f, smB = -1e30f;
#pragma unroll
        for (int nb = 0; nb < 8; nb++) {
            int2 m0 = *(const int2*)(mAp + k0 + nb * 8 + 2 * c);
            int2 m1 = *(const int2*)(mBp + k0 + nb * 8 + 2 * c);
            sa[nb][0] = m0.x ? sa[nb][0] : -1e9f;
            sa[nb][1] = m0.y ? sa[nb][1] : -1e9f;
            sa[nb][2] = m1.x ? sa[nb][2] : -1e9f;
            sa[nb][3] = m1.y ? sa[nb][3] : -1e9f;
            smA = fmaxf(smA, fmaxf(sa[nb][0], sa[nb][1]));
            smB = fmaxf(smB, fmaxf(sa[nb][2], sa[nb][3]));
        }
        smA = fmaxf(smA, __shfl_xor_sync(0xffffffffu, smA, 1));
        smA = fmaxf(smA, __shfl_xor_sync(0xffffffffu, smA, 2));
        smB = fmaxf(smB, __shfl_xor_sync(0xffffffffu, smB, 1));
        smB = fmaxf(smB, __shfl_xor_sync(0xffffffffu, smB, 2));

        float mnA = fmaxf(mxA, smA), mnB = fmaxf(mxB, smB);
        float aA = fast_exp(mxA - mnA), aB = fast_exp(mxB - mnB);
        mxA = mnA; mxB = mnB;

        float rsA = 0.f, rsB = 0.f;
#pragma unroll
        for (int nb = 0; nb < 8; nb++) {
            sa[nb][0] = fast_exp(sa[nb][0] - mnA);
            sa[nb][1] = fast_exp(sa[nb][1] - mnA);
            sa[nb][2] = fast_exp(sa[nb][2] - mnB);
            sa[nb][3] = fast_exp(sa[nb][3] - mnB);
            rsA += sa[nb][0] + sa[nb][1];
            rsB += sa[nb][2] + sa[nb][3];
        }
        rsA += __shfl_xor_sync(0xffffffffu, rsA, 1);
        rsA += __shfl_xor_sync(0xffffffffu, rsA, 2);
        rsB += __shfl_xor_sync(0xffffffffu, rsB, 1);
        rsB += __shfl_xor_sync(0xffffffffu, rsB, 2);
        lA = lA * aA + rsA;
        lB = lB * aB + rsB;

#pragma unroll
        for (int nb = 0; nb < 8; nb++) {
            O[nb][0] *= aA; O[nb][1] *= aA;
            O[nb][2] *= aB; O[nb][3] *= aB;
        }

        // O += P @ V : A-frags packed directly from C-frags (no shuffles)
#pragma unroll
        for (int kk = 0; kk < 4; kk++) {
            uint32_t af[4];
            af[0] = pack_h2(sa[2 * kk][0],     sa[2 * kk][1]);
            af[1] = pack_h2(sa[2 * kk][2],     sa[2 * kk][3]);
            af[2] = pack_h2(sa[2 * kk + 1][0], sa[2 * kk + 1][1]);
            af[3] = pack_h2(sa[2 * kk + 1][2], sa[2 * kk + 1][3]);
#pragma unroll
            for (int nb = 0; nb < 8; nb++) {
                int base = (nb * 8 + g) * KRS + 8 * kk + c;
                mma_f16(O[nb], af, Vs[base], Vs[base + 4]);
            }
        }
    }

    // Epilogue: normalize, write to g_attn [B,S,D]
    const float invA = 1.0f / lA, invB = 1.0f / lB;
    float* ogA = g_attn + ((size_t)b * Sn + rowA) * Dn + h * DKn;
    float* ogB = ogA + 8 * Dn;
#pragma unroll
    for (int nb = 0; nb < 8; nb++) {
        int col = nb * 8 + 2 * c;
        float2 va = {O[nb][0] * invA, O[nb][1] * invA};
        float2 vb = {O[nb][2] * invB, O[nb][3] * invB};
        *(float2*)&ogA[col] = va;
        *(float2*)&ogB[col] = vb;
    }
}

// ---------------------------------------------------------------------------
// kernel_launch: 5 kernel launches on the default stream (graph-capturable)
// ---------------------------------------------------------------------------
extern "C" void kernel_launch(void* const* d_in, const int* in_sizes, int n_in,
                              void* d_out, int out_size) {
    (void)in_sizes; (void)n_in; (void)out_size;
    const float* query = (const float*)d_in[0];
    const float* key   = (const float*)d_in[1];
    const float* value = (const float*)d_in[2];
    const int*   mask  = (const int*)d_in[3];
    const float* Wq = (const float*)d_in[4];
    const float* bq = (const float*)d_in[5];
    const float* Wk = (const float*)d_in[6];
    const float* bk = (const float*)d_in[7];
    const float* Wv = (const float*)d_in[8];
    const float* bv = (const float*)d_in[9];
    const float* Wo = (const float*)d_in[10];
    const float* bo = (const float*)d_in[11];

    dim3 gg(Dn / 128, Mn / 128);   // (8, 64)
    gemm_k<1><<<gg, 256>>>(query, Wq, bq, nullptr, 0);
    gemm_k<1><<<gg, 256>>>(key,   Wk, bk, nullptr, 1);
    gemm_k<1><<<gg, 256>>>(value, Wv, bv, nullptr, 2);

    attn_kernel<<<dim3(Sn / 128, Hn, Bn), 256>>>(mask);

    gemm_k<0><<<gg, 256>>>(nullptr, Wo, bo, (float*)d_out, 0);
}